// round 12
// baseline (speedup 1.0000x reference)
#include <cuda_runtime.h>
#include <cstdint>

// Problem shape (fixed by reference)
constexpr int B = 16, N = 8, M = 1024, F = 512;
constexpr int F4 = F / 4;              // 128 float4 columns
constexpr int M_CHUNK = 32;            // m-rows per block
constexpr int M_CHUNKS = M / M_CHUNK;  // 32
constexpr int N_FAULTS = 13;
constexpr float LOG2E = 1.4426950408889634f;

__device__ __forceinline__ float ex2_approx(float x) {
    float r;
    asm("ex2.approx.f32 %0, %1;" : "=f"(r) : "f"(x));
    return r;
}
__device__ __forceinline__ float rcp_approx(float x) {
    float r;
    asm("rcp.approx.f32 %0, %1;" : "=f"(r) : "f"(x));
    return r;
}

// One float4-column affine-tanh: out = p - q * rcp(ex2(z*c1+c0) + 1)
__device__ __forceinline__ float4 affine_tanh4(const float4 zv,
                                               const float* c1, const float* c0,
                                               const float* p,  const float* q) {
    float4 o;
    o.x = fmaf(-q[0], rcp_approx(ex2_approx(fmaf(zv.x, c1[0], c0[0])) + 1.0f), p[0]);
    o.y = fmaf(-q[1], rcp_approx(ex2_approx(fmaf(zv.y, c1[1], c0[1])) + 1.0f), p[1]);
    o.z = fmaf(-q[2], rcp_approx(ex2_approx(fmaf(zv.z, c1[2], c0[2])) + 1.0f), p[2]);
    o.w = fmaf(-q[3], rcp_approx(ex2_approx(fmaf(zv.w, c1[3], c0[3])) + 1.0f), p[3]);
    return o;
}

// ---------------------------------------------------------------------------
// One block = (b, n, mc) covering 32 m-rows; 128 threads = one float4
// f-column each, 32 rows streamed per thread. Grid 4096, 7 CTAs/SM
// (28 warps — the measured DRAM% optimum), depth-3 rotated pipeline
// (48 B/thread in flight during compute; R11 best point).
//
// vs R11: (a) __stcs on the write-once out stream (evict-first, frees L2
// for reads); (b) 32 rows/block halves prologue count and tail drains,
// waves 7.9 -> 3.95 with a 95%-full tail wave.
//
// Prologue: single dependent L2 trip — z rows prefetched first (covers the
// chain), speculative dual-width mask loads + detection loads in parallel,
// eta staged to smem (barrier shared with the detection OR).
//
// Mask dtype detection: values in [0,13) => int64 (LE) has every odd 32-bit
// word == 0; OR over 256 odd words nonzero for int32 w.p. 1-(1/13)^256.
// ---------------------------------------------------------------------------
__global__ __launch_bounds__(F4, 7)
void tanh_rt_kernel(const float4* __restrict__ z,
                    const int* __restrict__ mask32,
                    const float4* __restrict__ eta,   // [13] of (e0,e1,e2,e3)
                    float4* __restrict__ out) {
    __shared__ float4 s_eta[N_FAULTS];

    const int f4  = threadIdx.x;           // 0..127
    const int blk = blockIdx.x;
    const int mc  = blk % M_CHUNKS;
    const int bn  = blk / M_CHUNKS;        // 0..B*N-1
    const int b   = bn / N;

    const size_t base = ((size_t)bn * M + (size_t)mc * M_CHUNK) * F4 + f4;

    // --- (1) prefetch rows 0..2 (DRAM; covers the prologue chain) ---
    float4 a0 = z[base];
    float4 a1 = z[base + F4];
    float4 a2 = z[base + 2 * F4];

    // --- (2) speculative mask loads, both widths, all 4 f-lanes ---
    int m32v[4], m64v[4];
    #pragma unroll
    for (int j = 0; j < 4; j++) {
        const int pos = b * F + f4 * 4 + j;
        m32v[j] = mask32[pos];
        m64v[j] = mask32[2 * pos];
    }

    // --- (3) eta -> smem (13 threads, parallel) ---
    if (f4 < N_FAULTS) s_eta[f4] = eta[f4];

    // --- (4) detection loads + block OR; bar fences smem too ---
    unsigned acc = (unsigned)mask32[2 * f4 + 1] | (unsigned)mask32[2 * (f4 + 128) + 1];
    const int is64 = !__syncthreads_or((int)acc);

    // --- (5) register select + LDS gather + param math ---
    float c1[4], c0[4], p[4], q[4];
    #pragma unroll
    for (int j = 0; j < 4; j++) {
        const int midx = is64 ? m64v[j] : m32v[j];
        const float4 e = s_eta[midx];
        const float t1 = 2.0f * e.w * LOG2E;       // 2*e3*log2e
        c1[j] = t1;
        c0[j] = -e.z * t1;                         // -2*e2*e3*log2e
        p[j]  = e.x + e.y;                         // e0 + e1
        q[j]  = 2.0f * e.y;                        // 2*e1
    }

    // --- rotated loop, depth 3: rows 0..29 in 10 triples, tail rows 30,31 ---
    #pragma unroll
    for (int m = 0; m < 30; m += 3) {
        const float4 z0 = a0, z1 = a1, z2 = a2;
        const int nx = m + 3;
        if (nx < M_CHUNK)     a0 = z[base + (size_t)nx * F4];
        if (nx + 1 < M_CHUNK) a1 = z[base + (size_t)(nx + 1) * F4];
        if (nx + 2 < M_CHUNK) a2 = z[base + (size_t)(nx + 2) * F4];

        __stcs(&out[base + (size_t)m * F4],       affine_tanh4(z0, c1, c0, p, q));
        __stcs(&out[base + (size_t)(m + 1) * F4], affine_tanh4(z1, c1, c0, p, q));
        __stcs(&out[base + (size_t)(m + 2) * F4], affine_tanh4(z2, c1, c0, p, q));
    }
    // tail: rows 30, 31 (loaded into a0, a1 on the last iteration)
    __stcs(&out[base + (size_t)30 * F4], affine_tanh4(a0, c1, c0, p, q));
    __stcs(&out[base + (size_t)31 * F4], affine_tanh4(a1, c1, c0, p, q));
}

extern "C" void kernel_launch(void* const* d_in, const int* in_sizes, int n_in,
                              void* d_out, int out_size) {
    const float4* z      = (const float4*)d_in[0];
    const int*    mask32 = (const int*)d_in[1];      // int32 or int64, detected in-kernel
    const float4* eta    = (const float4*)d_in[2];   // [13,4] fp32
    float4*       out    = (float4*)d_out;

    tanh_rt_kernel<<<B * N * M_CHUNKS, F4>>>(z, mask32, eta, out);
}

// round 13
// speedup vs baseline: 1.0248x; 1.0248x over previous
#include <cuda_runtime.h>
#include <cstdint>

// Problem shape (fixed by reference)
constexpr int B = 16, N = 8, M = 1024, F = 512;
constexpr int F4 = F / 4;              // 128 float4 columns
constexpr int M_CHUNK = 32;            // m-rows per block (2 rows in parallel)
constexpr int M_CHUNKS = M / M_CHUNK;  // 32
constexpr int THREADS = 256;           // half*128 + f4
constexpr int N_FAULTS = 13;
constexpr float LOG2E = 1.4426950408889634f;

__device__ __forceinline__ float ex2_approx(float x) {
    float r;
    asm("ex2.approx.f32 %0, %1;" : "=f"(r) : "f"(x));
    return r;
}
__device__ __forceinline__ float rcp_approx(float x) {
    float r;
    asm("rcp.approx.f32 %0, %1;" : "=f"(r) : "f"(x));
    return r;
}

// ---------------------------------------------------------------------------
// FINAL (best measured wall config, R10): one block = (b, n, mc) covering
// 32 m-rows with 256 threads: lane f4 = t&127 picks the float4 f-column,
// half = t>>7 picks odd/even rows. Depth-2 rotated stream over 16 rows per
// thread; prologue collapsed to one dependent L2 trip and hidden under the
// initial z prefetch. 4 CTAs x 256 thr @ 64 regs = full RF, ~28-32 warps/SM
// (the measured DRAM% optimum of the warps x depth surface).
//
// Session surface (kernel us / dram%):
//   R2 base 78.2/77.9 | R6 rot2 76.3/79.7 | R9 +prologue 75.6/80.5 |
//   R10 merge 75.6/80.6 (wall best 82.40) | R11 depth3 75.3/80.7 |
//   rejected: reg-cap 80.1/76.4, persistent 82.4/74.3, depth4@6cta
//   77.5/78.6, 9cta 77.6/78.6, stcs+chunk32@128thr 77.0/79.0.
// Effective 537MB/75.6us = 7.1 TB/s ≈ 89% of spec — practical HBM ceiling.
//
// Mask dtype detection: values in [0,13) => int64 (LE) has every odd 32-bit
// word == 0; OR over 256 odd words nonzero for int32 w.p. 1-(1/13)^256.
// Speculative dual-width mask loads + eta staged to smem keep the prologue
// to a single dependent L2 trip.
//
// tanh(x) = 1 - 2/(exp(2x)+1)  ->  out = p - q * rcp(ex2(z*c1 + c0) + 1)
//   c1 = 2*e3*log2e, c0 = -2*e2*e3*log2e, p = e0+e1, q = 2*e1
// ---------------------------------------------------------------------------
__global__ __launch_bounds__(THREADS, 4)
void tanh_rt_kernel(const float4* __restrict__ z,
                    const int* __restrict__ mask32,
                    const float4* __restrict__ eta,   // [13] of (e0,e1,e2,e3)
                    float4* __restrict__ out) {
    __shared__ float4 s_eta[N_FAULTS];

    const int tid  = threadIdx.x;
    const int f4   = tid & 127;            // 0..127: float4 f-column
    const int half = tid >> 7;             // 0/1: even/odd rows
    const int blk  = blockIdx.x;
    const int mc   = blk % M_CHUNKS;
    const int bn   = blk / M_CHUNKS;       // 0..B*N-1
    const int b    = bn / N;

    // thread's first row: mc*32 + half; row stride = 2
    const size_t base = ((size_t)bn * M + (size_t)mc * M_CHUNK + half) * F4 + f4;
    const size_t RS = 2 * F4;              // row stride in float4

    // --- (1) prefetch this thread's rows 0,1 (DRAM; covers prologue) ---
    float4 a0 = z[base];
    float4 a1 = z[base + RS];

    // --- (2) speculative mask loads, both widths, all 4 f-lanes ---
    int m32v[4], m64v[4];
    #pragma unroll
    for (int j = 0; j < 4; j++) {
        const int pos = b * F + f4 * 4 + j;
        m32v[j] = mask32[pos];
        m64v[j] = mask32[2 * pos];
    }

    // --- (3) eta -> smem (13 threads, parallel) ---
    if (tid < N_FAULTS) s_eta[tid] = eta[tid];

    // --- (4) detection: 256 threads, 1 odd word each; bar fences smem ---
    unsigned acc = (unsigned)mask32[2 * tid + 1];
    const int is64 = !__syncthreads_or((int)acc);

    // --- (5) register select + LDS gather + param math ---
    float c1[4], c0[4], p[4], q[4];
    #pragma unroll
    for (int j = 0; j < 4; j++) {
        const int midx = is64 ? m64v[j] : m32v[j];
        const float4 e = s_eta[midx];
        const float t1 = 2.0f * e.w * LOG2E;       // 2*e3*log2e
        c1[j] = t1;
        c0[j] = -e.z * t1;                         // -2*e2*e3*log2e
        p[j]  = e.x + e.y;                         // e0 + e1
        q[j]  = 2.0f * e.y;                        // 2*e1
    }

    // --- rotated loop over this thread's 16 rows (stride-2 in m) ---
    #pragma unroll
    for (int i = 0; i < 16; i += 2) {
        const float4 z0 = a0;
        const float4 z1 = a1;
        if (i + 2 < 16) {
            a0 = z[base + (size_t)(i + 2) * RS];
            a1 = z[base + (size_t)(i + 3) * RS];
        }

        float4 o0, o1;
        o0.x = fmaf(-q[0], rcp_approx(ex2_approx(fmaf(z0.x, c1[0], c0[0])) + 1.0f), p[0]);
        o0.y = fmaf(-q[1], rcp_approx(ex2_approx(fmaf(z0.y, c1[1], c0[1])) + 1.0f), p[1]);
        o0.z = fmaf(-q[2], rcp_approx(ex2_approx(fmaf(z0.z, c1[2], c0[2])) + 1.0f), p[2]);
        o0.w = fmaf(-q[3], rcp_approx(ex2_approx(fmaf(z0.w, c1[3], c0[3])) + 1.0f), p[3]);

        o1.x = fmaf(-q[0], rcp_approx(ex2_approx(fmaf(z1.x, c1[0], c0[0])) + 1.0f), p[0]);
        o1.y = fmaf(-q[1], rcp_approx(ex2_approx(fmaf(z1.y, c1[1], c0[1])) + 1.0f), p[1]);
        o1.z = fmaf(-q[2], rcp_approx(ex2_approx(fmaf(z1.z, c1[2], c0[2])) + 1.0f), p[2]);
        o1.w = fmaf(-q[3], rcp_approx(ex2_approx(fmaf(z1.w, c1[3], c0[3])) + 1.0f), p[3]);

        out[base + (size_t)i * RS]       = o0;
        out[base + (size_t)(i + 1) * RS] = o1;
    }
}

extern "C" void kernel_launch(void* const* d_in, const int* in_sizes, int n_in,
                              void* d_out, int out_size) {
    const float4* z      = (const float4*)d_in[0];
    const int*    mask32 = (const int*)d_in[1];      // int32 or int64, detected in-kernel
    const float4* eta    = (const float4*)d_in[2];   // [13,4] fp32
    float4*       out    = (float4*)d_out;

    tanh_rt_kernel<<<B * N * M_CHUNKS, THREADS>>>(z, mask32, eta, out);
}